// round 6
// baseline (speedup 1.0000x reference)
#include <cuda_runtime.h>
#include <math_constants.h>

#define B_CONST 4096
#define D_CONST 256
#define N_CONST 8192
#define G1      128    // node-1 blocks (32 pairs each)

// scratch (device globals — allocation is forbidden; all overwritten each replay)
__device__ int   g_idxmax[N_CONST];
__device__ float g_maxfeat[N_CONST];
__device__ float g_partial[G1];     // per-block positive partial sums

__device__ __forceinline__ float pick4(float4 v, int s) {
    float r = v.x;
    if (s == 1) r = v.y;
    if (s == 2) r = v.z;
    if (s == 3) r = v.w;
    return r;
}

// Node 1: per-pair max/argmax + in-register positives. No atomics, no sync deps.
__global__ void __launch_bounds__(1024, 1)
rowstats_kernel(const float* __restrict__ a,
                const float* __restrict__ b,
                float* __restrict__ out, int out_n) {
    const int tid  = threadIdx.x;
    const int bid  = blockIdx.x;
    const int warp = tid >> 5;
    const int lane = tid & 31;
    const unsigned F = 0xffffffffu;

    __shared__ float s_pos[32];

    // zero output (poisoned 0xAA); node 2's atomics depend on this cross-node
    if (bid == 0 && tid < out_n) out[tid] = 0.0f;

    // warp handles pair (arow in a, arow in b) = rows (arow, arow+B)
    const int arow = bid * 32 + warp;              // 0..4095
    const float* r0 = a + (size_t)arow * D_CONST;
    const float* r1 = b + (size_t)arow * D_CONST;
    const int c0 = lane * 4;
    const int c1 = 128 + lane * 4;

    float4 v00 = *reinterpret_cast<const float4*>(r0 + c0);
    float4 v01 = *reinterpret_cast<const float4*>(r0 + c1);
    float4 v10 = *reinterpret_cast<const float4*>(r1 + c0);
    float4 v11 = *reinterpret_cast<const float4*>(r1 + c1);

    // per-lane best, increasing column order -> first-occurrence tie-break
    float best0 = v00.x; int bi0 = c0;
    if (v00.y > best0) { best0 = v00.y; bi0 = c0 + 1; }
    if (v00.z > best0) { best0 = v00.z; bi0 = c0 + 2; }
    if (v00.w > best0) { best0 = v00.w; bi0 = c0 + 3; }
    if (v01.x > best0) { best0 = v01.x; bi0 = c1;     }
    if (v01.y > best0) { best0 = v01.y; bi0 = c1 + 1; }
    if (v01.z > best0) { best0 = v01.z; bi0 = c1 + 2; }
    if (v01.w > best0) { best0 = v01.w; bi0 = c1 + 3; }

    float best1 = v10.x; int bi1 = c0;
    if (v10.y > best1) { best1 = v10.y; bi1 = c0 + 1; }
    if (v10.z > best1) { best1 = v10.z; bi1 = c0 + 2; }
    if (v10.w > best1) { best1 = v10.w; bi1 = c0 + 3; }
    if (v11.x > best1) { best1 = v11.x; bi1 = c1;     }
    if (v11.y > best1) { best1 = v11.y; bi1 = c1 + 1; }
    if (v11.z > best1) { best1 = v11.z; bi1 = c1 + 2; }
    if (v11.w > best1) { best1 = v11.w; bi1 = c1 + 3; }

    // warp reduce: max value, min index on ties (matches jnp.argmax)
    #pragma unroll
    for (int off = 16; off; off >>= 1) {
        float ov0 = __shfl_down_sync(F, best0, off);
        int   oi0 = __shfl_down_sync(F, bi0,   off);
        float ov1 = __shfl_down_sync(F, best1, off);
        int   oi1 = __shfl_down_sync(F, bi1,   off);
        if (ov0 > best0 || (ov0 == best0 && oi0 < bi0)) { best0 = ov0; bi0 = oi0; }
        if (ov1 > best1 || (ov1 == best1 && oi1 < bi1)) { best1 = ov1; bi1 = oi1; }
    }
    // broadcast winners to all lanes
    const float m0 = __shfl_sync(F, best0, 0);
    const int   j0 = __shfl_sync(F, bi0,   0);
    const float m1 = __shfl_sync(F, best1, 0);
    const int   j1 = __shfl_sync(F, bi1,   0);

    // positives in-register:
    //   pos_a = max_a - row_a[idxmax_b] ; pos_b = max_b - row_b[idxmax_a]
    // element extraction: owner lane of column j is ((j & 127) >> 2)
    float xa = pick4(v00, j1 & 3), ya = pick4(v01, j1 & 3);
    float fa = __shfl_sync(F, (j1 < 128) ? xa : ya, (j1 >> 2) & 31);
    float xb = pick4(v10, j0 & 3), yb = pick4(v11, j0 & 3);
    float fb = __shfl_sync(F, (j0 < 128) ? xb : yb, (j0 >> 2) & 31);
    const float pos_sum = (m0 - fa) + (m1 - fb);

    if (lane == 0) {
        g_idxmax[arow]            = j0;
        g_maxfeat[arow]           = m0;
        g_idxmax[arow + B_CONST]  = j1;
        g_maxfeat[arow + B_CONST] = m1;
        s_pos[warp] = pos_sum;
    }
    __syncthreads();
    if (warp == 0) {
        float v = s_pos[lane];
        #pragma unroll
        for (int off = 16; off; off >>= 1)
            v += __shfl_down_sync(F, v, off);
        if (lane == 0) g_partial[bid] = v;   // plain store, replay-safe
    }
}

// Node 2: negatives + histogram + final reduction. Kernel boundary = grid sync.
__global__ void __launch_bounds__(128, 1)
finalize_kernel(const float* __restrict__ a,
                const float* __restrict__ b,
                const int*   __restrict__ negc,
                float* __restrict__ out) {
    const int tid = threadIdx.x;
    const int i   = blockIdx.x * 128 + tid;      // row 0..8191
    const int lane = tid & 31;

    // independent loads first
    const int   ji = g_idxmax[i];
    const float mf = g_maxfeat[i];
    int c = negc[i];

    const int pair = i ^ B_CONST;                // (i+B) mod N, N=2B pow2
    const int e1 = min(i, pair);
    const int e2 = max(i, pair);
    c += (c >= e1) ? 1 : 0;
    c += (c >= e2) ? 1 : 0;

    const int j2 = g_idxmax[c];                  // dependent L2 load
    const float* row = (i < B_CONST)
        ? (a + (size_t)i * D_CONST)
        : (b + (size_t)(i - B_CONST) * D_CONST);
    const float neg = mf - row[j2];              // dependent (L2-hot) load
    const float m   = fmaxf(1.0f - neg, 0.0f);
    float contrib = m * m;

    // fold in node-1 positive partials (block 0 threads 0..127 <-> G1=128)
    if (blockIdx.x == 0) contrib += g_partial[tid];

    atomicAdd(&out[1 + ji], 1.0f);               // num_max histogram

    // block reduce (128 threads = 4 warps)
    __shared__ float sm[4];
    #pragma unroll
    for (int off = 16; off; off >>= 1)
        contrib += __shfl_down_sync(0xffffffffu, contrib, off);
    if (lane == 0) sm[tid >> 5] = contrib;
    __syncthreads();
    if (tid == 0) {
        float v = sm[0] + sm[1] + sm[2] + sm[3];
        atomicAdd(&out[0], 0.5f * v);            // sum(...)/2
    }
}

extern "C" void kernel_launch(void* const* d_in, const int* in_sizes, int n_in,
                              void* d_out, int out_size) {
    const float* a    = (const float*)d_in[0];   // out_a [4096,256] f32
    const float* b    = (const float*)d_in[1];   // out_b [4096,256] f32
    const int*   negc = (const int*)  d_in[2];   // neg_choice [8192] i32
    float* out = (float*)d_out;

    rowstats_kernel<<<G1, 1024>>>(a, b, out, out_size);
    finalize_kernel<<<N_CONST / 128, 128>>>(a, b, negc, out);
}